// round 7
// baseline (speedup 1.0000x reference)
#include <cuda_runtime.h>
#include <math.h>

// ---------------------------------------------------------------------------
// Problem: b=2, c=512, h=w=64 -> n=4096 points, d=64 features, 5x5 local cov.
// out[b] = concat(mu (64 ch), local cov (25 ch)) -> (2, 89, 64, 64) fp32.
//
// Method per batch:
//   K_yy+sigma*I = L L^T (blocked Cholesky, NB=128, diag blocks inverted)
//   X  = [K_xy ; ff^T] * L^{-T}   (right-TRSM, M=4224 rows)
//   mu = X(0:4096) @ X(4096:4160)^T
//   cov[p,q] = K_xx[p,q] - X[p,:].X[q,:]   (only 5x5 neighbors)
// ---------------------------------------------------------------------------

#define NPT   4096
#define MROWS 4224          // 4096 Kxy rows + 64 ff rows + 64 zero pad
#define NBLK  32            // 4096/128

__device__ float g_L   [(size_t)NPT * NPT];      // K_yy -> L (lower)
__device__ float g_X   [(size_t)MROWS * NPT];    // K_xy/ff^T -> X / u^T
__device__ float g_Linv[32 * 128 * 128];         // per-block-diag L^{-1}
__device__ float g_XF  [(size_t)NPT * 512];      // x point-major (p, ch)
__device__ float g_MU  [(size_t)NPT * 128];      // mu staging (p, dch)
__device__ float g_xn  [NPT];
__device__ float g_yn  [NPT];

// ---------------- small prep kernels ----------------
__global__ void norms_k(const float* __restrict__ v, float* __restrict__ o) {
    int p = blockIdx.x * blockDim.x + threadIdx.x;
    float s = 0.f;
    for (int ch = 0; ch < 512; ch++) { float t = v[(size_t)ch * NPT + p]; s += t * t; }
    o[p] = sqrtf(s);
}

__global__ void transpose_k(const float* __restrict__ v, float* __restrict__ o) {
    __shared__ float t[32][33];
    int pb = blockIdx.x * 32, cb = blockIdx.y * 32;
    for (int yy = threadIdx.y; yy < 32; yy += 8)
        t[yy][threadIdx.x] = v[(size_t)(cb + yy) * NPT + pb + threadIdx.x];
    __syncthreads();
    for (int yy = threadIdx.y; yy < 32; yy += 8)
        o[(size_t)(pb + yy) * 512 + cb + threadIdx.x] = t[threadIdx.x][yy];
}

__global__ void features_k(const float* __restrict__ pw, const float* __restrict__ pb,
                           float* __restrict__ F) {
    int idx = blockIdx.x * blockDim.x + threadIdx.x;   // 4096*64
    int q = idx & 4095, dch = idx >> 12;
    float gx = (2.f * (float)(q & 63) + 1.f) * (1.f / 64.f) - 1.f;
    float gy = (2.f * (float)(q >> 6) + 1.f) * (1.f / 64.f) - 1.f;
    float ph = pw[dch * 2 + 0] * gx + pw[dch * 2 + 1] * gy + pb[dch];
    F[(size_t)dch * NPT + q] = cosf(25.132741228718345f * ph);   // 8*pi
}

__global__ void zero_rows(float* __restrict__ dst) {
    int i = blockIdx.x * blockDim.x + threadIdx.x;     // 64*4096
    dst[i] = 0.f;
}

__global__ void copy_mu(const float* __restrict__ MU, float* __restrict__ out) {
    int idx = blockIdx.x * blockDim.x + threadIdx.x;   // 64*4096
    int dch = idx >> 12, p = idx & 4095;
    out[(size_t)dch * NPT + p] = MU[(size_t)p * 128 + dch];
}

// ---------------- Gram: C[p,q] = exp(dot/(na nb + eps) - 1) (+sigma diag) ----
// A,B channel-major (512 x 4096). 128x128x8 tiles, 256 threads.
__global__ void __launch_bounds__(256) gram_tn(const float* __restrict__ A,
        const float* __restrict__ B, float* __restrict__ Cm,
        const float* __restrict__ na, const float* __restrict__ nb,
        int lowerOnly, float sigmaDiag) {
    int bx = blockIdx.x, by = blockIdx.y;
    if (lowerOnly && bx > by) return;
    __shared__ float As[8][128], Bs[8][128];
    int tid = threadIdx.x;
    int tx = tid & 15, ty = tid >> 4;
    const float* Ab = A + by * 128;
    const float* Bb = B + bx * 128;
    float acc[8][8];
    #pragma unroll
    for (int i = 0; i < 8; i++)
        #pragma unroll
        for (int j = 0; j < 8; j++) acc[i][j] = 0.f;
    int lr = tid >> 5;            // k row 0..7
    int lc = (tid & 31) << 2;     // col 0..124
    for (int k0 = 0; k0 < 512; k0 += 8) {
        float4 av = *(const float4*)(Ab + (size_t)(k0 + lr) * NPT + lc);
        float4 bv = *(const float4*)(Bb + (size_t)(k0 + lr) * NPT + lc);
        *(float4*)&As[lr][lc] = av;
        *(float4*)&Bs[lr][lc] = bv;
        __syncthreads();
        #pragma unroll
        for (int k = 0; k < 8; k++) {
            float a[8], b[8];
            *(float4*)(a)     = *(const float4*)&As[k][ty * 8];
            *(float4*)(a + 4) = *(const float4*)&As[k][ty * 8 + 4];
            *(float4*)(b)     = *(const float4*)&Bs[k][tx * 8];
            *(float4*)(b + 4) = *(const float4*)&Bs[k][tx * 8 + 4];
            #pragma unroll
            for (int i = 0; i < 8; i++)
                #pragma unroll
                for (int j = 0; j < 8; j++) acc[i][j] += a[i] * b[j];
        }
        __syncthreads();
    }
    #pragma unroll
    for (int i = 0; i < 8; i++) {
        int gi = by * 128 + ty * 8 + i;
        float nai = na[gi];
        #pragma unroll
        for (int j = 0; j < 8; j++) {
            int gj = bx * 128 + tx * 8 + j;
            float v = expf(acc[i][j] / (nai * nb[gj] + 1e-6f) - 1.f);
            if (gi == gj) v += sigmaDiag;
            Cm[(size_t)gi * NPT + gj] = v;
        }
    }
}

// ---------------- GEMM-NT: mode 0: C -= A*B^T ; mode 1: C = A*B^T ------------
// Row-major. M blocks on grid.y, N blocks on grid.x. K multiple of 8.
// Safe for in-place C==A when mode==1 and gridDim.x==1 (reads staged via smem,
// writes only in epilogue).
__global__ void __launch_bounds__(256) gemm_nt(const float* __restrict__ A,
        const float* __restrict__ B, float* __restrict__ Cm,
        int K, int lda, int ldb, int ldc, int mode, int triSkip) {
    int bx = blockIdx.x, by = blockIdx.y;
    if (triSkip && bx > by) return;
    __shared__ float As[8][128], Bs[8][128];
    int tid = threadIdx.x;
    int tx = tid & 15, ty = tid >> 4;
    const float* Ab = A + (size_t)(by * 128) * lda;
    const float* Bb = B + (size_t)(bx * 128) * ldb;
    float* Cb = Cm + (size_t)(by * 128) * ldc + bx * 128;
    float acc[8][8];
    #pragma unroll
    for (int i = 0; i < 8; i++)
        #pragma unroll
        for (int j = 0; j < 8; j++) acc[i][j] = 0.f;
    int lr = tid >> 1;            // row 0..127
    int lc = (tid & 1) << 2;      // k offset 0 or 4
    for (int k0 = 0; k0 < K; k0 += 8) {
        float4 av = *(const float4*)(Ab + (size_t)lr * lda + k0 + lc);
        float4 bv = *(const float4*)(Bb + (size_t)lr * ldb + k0 + lc);
        As[lc + 0][lr] = av.x; As[lc + 1][lr] = av.y; As[lc + 2][lr] = av.z; As[lc + 3][lr] = av.w;
        Bs[lc + 0][lr] = bv.x; Bs[lc + 1][lr] = bv.y; Bs[lc + 2][lr] = bv.z; Bs[lc + 3][lr] = bv.w;
        __syncthreads();
        #pragma unroll
        for (int k = 0; k < 8; k++) {
            float a[8], b[8];
            *(float4*)(a)     = *(const float4*)&As[k][ty * 8];
            *(float4*)(a + 4) = *(const float4*)&As[k][ty * 8 + 4];
            *(float4*)(b)     = *(const float4*)&Bs[k][tx * 8];
            *(float4*)(b + 4) = *(const float4*)&Bs[k][tx * 8 + 4];
            #pragma unroll
            for (int i = 0; i < 8; i++)
                #pragma unroll
                for (int j = 0; j < 8; j++) acc[i][j] += a[i] * b[j];
        }
        __syncthreads();
    }
    if (mode == 0) {
        #pragma unroll
        for (int i = 0; i < 8; i++) {
            float4* cp = (float4*)(Cb + (size_t)(ty * 8 + i) * ldc + tx * 8);
            float4 v0 = cp[0], v1 = cp[1];
            v0.x -= acc[i][0]; v0.y -= acc[i][1]; v0.z -= acc[i][2]; v0.w -= acc[i][3];
            v1.x -= acc[i][4]; v1.y -= acc[i][5]; v1.z -= acc[i][6]; v1.w -= acc[i][7];
            cp[0] = v0; cp[1] = v1;
        }
    } else {
        #pragma unroll
        for (int i = 0; i < 8; i++) {
            float4 v0, v1;
            v0.x = acc[i][0]; v0.y = acc[i][1]; v0.z = acc[i][2]; v0.w = acc[i][3];
            v1.x = acc[i][4]; v1.y = acc[i][5]; v1.z = acc[i][6]; v1.w = acc[i][7];
            float4* cp = (float4*)(Cb + (size_t)(ty * 8 + i) * ldc + tx * 8);
            cp[0] = v0; cp[1] = v1;
        }
    }
}

// ---------------- 128x128 diagonal Cholesky + triangular inverse -------------
// One block, 128 threads. Reads/writes the diag block of g_L (lda=4096) and
// writes L^{-1} (row-major 128x128, upper zeros) to Inv.
__global__ void __launch_bounds__(128) potf2_inv(float* __restrict__ Ablk,
                                                 float* __restrict__ Inv) {
    extern __shared__ float sm[];
    float* As = sm;                 // stride 129
    float* Iv = sm + 128 * 129;     // stride 128
    int tid = threadIdx.x;
    for (int idx = tid; idx < 128 * 128; idx += 128) {
        int r = idx >> 7, c = idx & 127;
        As[r * 129 + c] = Ablk[(size_t)r * NPT + c];
    }
    __syncthreads();
    for (int j = 0; j < 128; j++) {
        if (tid == 0) As[j * 129 + j] = sqrtf(As[j * 129 + j]);
        __syncthreads();
        float d = As[j * 129 + j];
        if (tid > j) As[tid * 129 + j] /= d;
        __syncthreads();
        int m = j + 1 + tid;
        if (m < 128) {
            float lm = As[m * 129 + j];
            #pragma unroll 4
            for (int t = j + 1; t < 128; t++)
                As[t * 129 + m] -= As[t * 129 + j] * lm;
        }
        __syncthreads();
    }
    // column-parallel forward substitution: Iv[:,c] solves L x = e_c
    {
        int c = tid;
        for (int t = 0; t < c; t++) Iv[t * 128 + c] = 0.f;
        Iv[c * 128 + c] = 1.f / As[c * 129 + c];
        for (int t = c + 1; t < 128; t++) {
            float s = 0.f;
            for (int m2 = c; m2 < t; m2++) s += As[t * 129 + m2] * Iv[m2 * 128 + c];
            Iv[t * 128 + c] = -s / As[t * 129 + t];
        }
    }
    __syncthreads();
    for (int idx = tid; idx < 128 * 128; idx += 128) {
        int r = idx >> 7, c = idx & 127;
        Ablk[(size_t)r * NPT + c] = As[r * 129 + c];
        Inv[idx] = Iv[idx];
    }
}

// ---------------- local covariance + Kxx on 5x5 neighborhoods ----------------
__global__ void __launch_bounds__(256) local_k(const float* __restrict__ X,
        const float* __restrict__ XF, const float* __restrict__ xn,
        float* __restrict__ outb) {
    __shared__ __align__(16) float sXp[4096];
    __shared__ __align__(16) float sXf[512];
    __shared__ float sRed[16];
    int p = blockIdx.x, tid = threadIdx.x;
    const float4* Xp4 = (const float4*)(X + (size_t)p * NPT);
    for (int t = tid; t < 1024; t += 256) ((float4*)sXp)[t] = Xp4[t];
    const float4* xf4 = (const float4*)(XF + (size_t)p * 512);
    if (tid < 128) ((float4*)sXf)[tid] = xf4[tid];
    __syncthreads();
    int i0 = p >> 6, j0 = p & 63;
    float nxp = xn[p];
    int warp = tid >> 5, lane = tid & 31;
    for (int kk = 0; kk < 25; kk++) {
        int dr = kk / 5 - 2, dc = kk % 5 - 2;
        int qi = i0 + dr, qj = j0 + dc;
        bool valid = (qi >= 0) & (qi < 64) & (qj >= 0) & (qj < 64);
        __syncthreads();
        if (!valid) {
            if (tid == 0) outb[(size_t)(64 + kk) * NPT + p] = 0.f;
            continue;
        }
        int q = qi * 64 + qj;
        const float4* Xq4 = (const float4*)(X + (size_t)q * NPT);
        float s = 0.f;
        for (int t = tid; t < 1024; t += 256) {
            float4 a = ((const float4*)sXp)[t];
            float4 bq = Xq4[t];
            s += a.x * bq.x + a.y * bq.y + a.z * bq.z + a.w * bq.w;
        }
        float s2 = 0.f;
        const float4* xq4 = (const float4*)(XF + (size_t)q * 512);
        if (tid < 128) {
            float4 a = ((const float4*)sXf)[tid];
            float4 bq = xq4[tid];
            s2 = a.x * bq.x + a.y * bq.y + a.z * bq.z + a.w * bq.w;
        }
        #pragma unroll
        for (int o = 16; o; o >>= 1) {
            s  += __shfl_down_sync(0xffffffffu, s,  o);
            s2 += __shfl_down_sync(0xffffffffu, s2, o);
        }
        if (lane == 0) { sRed[warp] = s; sRed[8 + warp] = s2; }
        __syncthreads();
        if (tid == 0) {
            float ts = 0.f, ts2 = 0.f;
            #pragma unroll
            for (int w = 0; w < 8; w++) { ts += sRed[w]; ts2 += sRed[8 + w]; }
            float kxx = expf(ts2 / (nxp * xn[q] + 1e-6f) - 1.f);
            outb[(size_t)(64 + kk) * NPT + p] = kxx - ts;
        }
    }
}

// ---------------------------------------------------------------------------
extern "C" void kernel_launch(void* const* d_in, const int* in_sizes, int n_in,
                              void* d_out, int out_size) {
    const float* x  = (const float*)d_in[0];
    const float* y  = (const float*)d_in[1];
    const float* pw = (const float*)d_in[2];
    const float* pb = (const float*)d_in[3];
    float* out = (float*)d_out;
    (void)in_sizes; (void)n_in; (void)out_size;

    float *pL, *pX, *pLi, *pXF, *pMU, *pxn, *pyn;
    cudaGetSymbolAddress((void**)&pL,  g_L);
    cudaGetSymbolAddress((void**)&pX,  g_X);
    cudaGetSymbolAddress((void**)&pLi, g_Linv);
    cudaGetSymbolAddress((void**)&pXF, g_XF);
    cudaGetSymbolAddress((void**)&pMU, g_MU);
    cudaGetSymbolAddress((void**)&pxn, g_xn);
    cudaGetSymbolAddress((void**)&pyn, g_yn);

    const int PSMEM = 128 * 129 * 4 + 128 * 128 * 4;
    cudaFuncSetAttribute(potf2_inv, cudaFuncAttributeMaxDynamicSharedMemorySize, PSMEM);

    for (int b = 0; b < 2; b++) {
        const float* xb = x + (size_t)b * 512 * NPT;
        const float* yb = y + (size_t)b * 512 * NPT;
        float* outb = out + (size_t)b * 89 * NPT;

        norms_k<<<16, 256>>>(xb, pxn);
        norms_k<<<16, 256>>>(yb, pyn);
        transpose_k<<<dim3(128, 16), dim3(32, 8)>>>(xb, pXF);

        // K_yy (lower, +sigma) and K_xy (full)
        gram_tn<<<dim3(32, 32), 256>>>(yb, yb, pL, pyn, pyn, 1, 0.1f);
        gram_tn<<<dim3(32, 32), 256>>>(xb, yb, pX, pxn, pyn, 0, 0.f);

        // ff^T rows + zero pad rows of the RHS block
        features_k<<<1024, 256>>>(pw, pb, pX + (size_t)NPT * NPT);
        zero_rows<<<1024, 256>>>(pX + (size_t)(NPT + 64) * NPT);

        // ---- blocked Cholesky of K_yy + sigma I ----
        for (int k = 0; k < NBLK; k++) {
            float* diag  = pL + (size_t)k * 128 * NPT + k * 128;
            float* linv  = pLi + k * 128 * 128;
            potf2_inv<<<1, 128, PSMEM>>>(diag, linv);
            if (k < NBLK - 1) {
                int rem = NBLK - 1 - k;
                float* panel = pL + (size_t)(k + 1) * 128 * NPT + k * 128;
                // panel TRSM: L[i,k] = A[i,k] * Linv^T   (in place)
                gemm_nt<<<dim3(1, rem), 256>>>(panel, linv, panel,
                                               128, NPT, 128, NPT, 1, 0);
                // trailing SYRK (lower): A[i,j] -= L[i,k] L[j,k]^T
                float* trail = pL + (size_t)(k + 1) * 128 * NPT + (k + 1) * 128;
                gemm_nt<<<dim3(rem, rem), 256>>>(panel, panel, trail,
                                                 128, NPT, NPT, NPT, 0, 1);
            }
        }

        // ---- right-TRSM: X * L^T = B, column-block forward sweep ----
        for (int k = 0; k < NBLK; k++) {
            float* col  = pX + k * 128;
            float* linv = pLi + k * 128 * 128;
            gemm_nt<<<dim3(1, MROWS / 128), 256>>>(col, linv, col,
                                                   128, NPT, 128, NPT, 1, 0);
            if (k < NBLK - 1) {
                int rem = NBLK - 1 - k;
                float* w = pL + (size_t)(k + 1) * 128 * NPT + k * 128;
                float* c = pX + (k + 1) * 128;
                gemm_nt<<<dim3(rem, MROWS / 128), 256>>>(col, w, c,
                                                         128, NPT, NPT, NPT, 0, 0);
            }
        }

        // ---- mu = X(0:4096) @ u, u^T = rows 4096..4223 (pad rows are zero) ----
        gemm_nt<<<dim3(1, 32), 256>>>(pX, pX + (size_t)NPT * NPT, pMU,
                                      NPT, NPT, NPT, 128, 1, 0);
        copy_mu<<<1024, 256>>>(pMU, outb);

        // ---- local covariance channels ----
        local_k<<<4096, 256>>>(pX, pXF, pxn, outb);
    }
}